// round 6
// baseline (speedup 1.0000x reference)
#include <cuda_runtime.h>
#include <math.h>

#define BB 8
#define H 256
#define W 256
#define NPIX (H*W)
#define GRID 512

// Scratch (device globals — no allocation allowed)
__device__ unsigned int g_cm[BB*W*8];   // column seed masks: [(b*W+j)*8 + slab]
__device__ float g_pd[GRID];            // per-block sum(pred*d)
__device__ float g_d [GRID];            // per-block sum(d)
__device__ float g_mx[GRID];            // per-block max(d)
__device__ unsigned int g_barA = 0;     // phase-A arrival counter
__device__ unsigned int g_ticket = 0;   // phase-B completion counter

union SmemU {
    struct {                            // phase A: rows row0-1 .. row0+32
        unsigned int tb[34];
        unsigned int hm[34];
    } a;
    struct {                            // phase B: 4 rows, each padded [W|W|W]
        float s[4][3*W];
    } b;
};

__global__ void __launch_bounds__(256, 4)
k_fused(const float* __restrict__ logits, const int* __restrict__ target,
        float* __restrict__ out) {
    __shared__ SmemU u;
    __shared__ float rs[8], rp[8], rm[8];
    __shared__ bool amLast;

    int bid = blockIdx.x;
    int tid = threadIdx.x;
    int w = tid >> 5, lane = tid & 31;

    // ====== Phase A (ALL 512 blocks): (image, col-group, row-slab) stripe ===
    {
        int b    = bid >> 6;            // image 0..7
        int g    = (bid >> 3) & 7;      // 32-col group
        int slab = bid & 7;             // 32-row slab
        int colbase = g << 5;
        int row0 = slab << 5;
        const int* t = target + b * NPIX;

        // pack + horizontal 3-AND for rows row0-1 .. row0+32 (34 rows)
        for (int i = w; i < 34; i += 8) {
            int gi = row0 - 1 + i;
            unsigned int m = 0u, hm = 0u;
            if (gi >= 0 && gi < H) {
                int v = t[gi * W + colbase + lane];
                m = __ballot_sync(0xffffffffu, v != 0);
                int Lv = 0, Rv = 0;
                if (lane == 0  && g > 0) Lv = t[gi * W + colbase - 1];
                if (lane == 31 && g < 7) Rv = t[gi * W + colbase + 32];
                unsigned int Lb = __shfl_sync(0xffffffffu, Lv != 0 ? 1u : 0u, 0);
                unsigned int Rb = __shfl_sync(0xffffffffu, Rv != 0 ? 1u : 0u, 31);
                hm = m & ((m << 1) | Lb) & ((m >> 1) | (Rb << 31));
            }
            if (lane == 0) { u.a.tb[i] = m; u.a.hm[i] = hm; }
        }
        __syncthreads();

        // warp 0: erosion + boundary for the slab's 32 rows, then 32x32
        // bit-transpose so lane j holds column (colbase+j)'s slab seed bits.
        if (w == 0) {
            int gr = row0 + lane;
            unsigned int er = u.a.hm[lane] & u.a.hm[lane + 1] & u.a.hm[lane + 2];
            if (gr == 0 || gr == H - 1) er = 0u;
            if (g == 0) er &= ~1u;
            if (g == 7) er &= ~(1u << 31);
            unsigned int word = u.a.tb[lane + 1] ^ er;

            unsigned int v = 0u;
            #pragma unroll
            for (int jj = 0; jj < 32; jj++) {
                unsigned int bm = __ballot_sync(0xffffffffu, (word >> jj) & 1u);
                if (lane == jj) v = bm;
            }
            g_cm[((b * W) + colbase + lane) * 8 + slab] = v;
            __threadfence();
        }
        __syncthreads();
        if (tid == 0) atomicAdd(&g_barA, 1u);
    }

    // ====== Prefetch logits (independent of phase A) ========================
    int b = bid >> 6;                   // image
    int i0 = (bid & 63) * 4;            // first of 4 rows (same 32-row slab)
    int j = tid;                        // column
    float xl[4];
    #pragma unroll
    for (int r = 0; r < 4; r++)
        xl[r] = logits[(b * H + i0 + r) * W + j];

    // ====== Grid barrier (all 512 blocks co-resident) =======================
    if (tid == 0) {
        while (*(volatile unsigned int*)&g_barA < GRID) __nanosleep(32);
    }
    __syncthreads();

    // ====== Phase B: vertical distance from bitmask + exact min-plus ========
    const uint4* cmp = (const uint4*)&g_cm[((b * W) + j) * 8];
    uint4 lov = cmp[0], hiv = cmp[1];
    unsigned int cm[8] = {lov.x, lov.y, lov.z, lov.w, hiv.x, hiv.y, hiv.z, hiv.w};

    int ws = i0 >> 5;
    int P = -1000000, N = 1000000;
    #pragma unroll
    for (int k = 0; k < 8; k++) {
        if (k < ws && cm[k]) P = (k << 5) + 31 - __clz(cm[k]);
        if (k > ws && cm[k] && N == 1000000) N = (k << 5) + __ffs(cm[k]) - 1;
    }
    unsigned int vw = cm[ws];

    #pragma unroll
    for (int r = 0; r < 4; r++) {
        int i = i0 + r, bi = i & 31;
        unsigned int below = vw & (0xFFFFFFFFu >> (31 - bi));
        unsigned int above = vw & (0xFFFFFFFFu << bi);
        int last = below ? ((ws << 5) + 31 - __clz(below)) : P;
        int nxt  = above ? ((ws << 5) + __ffs(above) - 1)  : N;
        int f = min(min(i - last, nxt - i), 10000);      // BIG clip (1e4)
        u.b.s[r][j] = 1e30f;                             // left pad
        u.b.s[r][2 * W + j] = 1e30f;                     // right pad
        u.b.s[r][W + j] = (float)(f * f);                // exact in fp32
    }
    __syncthreads();

    // exact min-plus per pixel, per-lane early exit
    float sd = 0.f, sp = 0.f, mxv = 0.f;
    #pragma unroll
    for (int r = 0; r < 4; r++) {
        const float* s = u.b.s[r];
        float m = s[W + j];
        int o = 1;
        while ((float)(o * o) < m) {
            float o2 = (float)(o * o);
            m = fminf(m, s[W + j - o] + o2);
            m = fminf(m, s[W + j + o] + o2);
            o++;
        }
        float d = sqrtf(m);
        float pred = 1.f / (1.f + __expf(-xl[r]));
        sd += d;
        sp += pred * d;
        mxv = fmaxf(mxv, d);
    }

    // deterministic block reduction -> per-block partials
    #pragma unroll
    for (int o = 16; o; o >>= 1) {
        sd  += __shfl_down_sync(0xffffffffu, sd,  o);
        sp  += __shfl_down_sync(0xffffffffu, sp,  o);
        mxv  = fmaxf(mxv, __shfl_down_sync(0xffffffffu, mxv, o));
    }
    if (lane == 0) { rs[w] = sd; rp[w] = sp; rm[w] = mxv; }
    __syncthreads();
    if (tid == 0) {
        float S = 0.f, Pp = 0.f, M = 0.f;
        #pragma unroll
        for (int k = 0; k < 8; k++) { S += rs[k]; Pp += rp[k]; M = fmaxf(M, rm[k]); }
        g_d[bid] = S; g_pd[bid] = Pp; g_mx[bid] = M;
        __threadfence();
        unsigned int tk = atomicAdd(&g_ticket, 1u);
        amLast = (tk == GRID - 1);
    }
    __syncthreads();
    if (!amLast) return;

    // ====== Final reduction (last block), deterministic =====================
    {
        double sdd = 0.0, spp = 0.0;
        float mxx = 0.f;
        #pragma unroll
        for (int k = 0; k < 2; k++) {
            int rr = w * 64 + k * 32 + lane;
            sdd += (double)g_d[rr];
            spp += (double)g_pd[rr];
            mxx = fmaxf(mxx, g_mx[rr]);
        }
        #pragma unroll
        for (int o = 16; o; o >>= 1) {
            sdd += __shfl_down_sync(0xffffffffu, sdd, o);
            spp += __shfl_down_sync(0xffffffffu, spp, o);
            mxx  = fmaxf(mxx, __shfl_down_sync(0xffffffffu, mxx, o));
        }
        __shared__ double sper[BB];
        if (lane == 0)
            sper[w] = spp / (sdd + 1e-7 * ((double)mxx + 1e-7));
        __syncthreads();
        if (tid == 0) {
            double acc = 0.0;
            #pragma unroll
            for (int k = 0; k < BB; k++) acc += sper[k];
            out[0] = (float)(acc / BB);
            g_ticket = 0;                 // reset for next graph replay
            g_barA = 0;
        }
    }
}

extern "C" void kernel_launch(void* const* d_in, const int* in_sizes, int n_in,
                              void* d_out, int out_size) {
    const float* logits = (const float*)d_in[0];
    const int*   target = (const int*)d_in[1];
    float* out = (float*)d_out;

    k_fused<<<GRID, 256>>>(logits, target, out);
}

// round 7
// speedup vs baseline: 1.1056x; 1.1056x over previous
#include <cuda_runtime.h>
#include <math.h>

#define BB 8
#define H 256
#define W 256
#define NPIX (H*W)
#define GRID 512
#define PREP_BLOCKS 64

// Scratch (device globals — no allocation allowed)
__device__ unsigned int g_cm[BB*W*8];   // column seed masks: [(b*W+j)*8 + slab]
__device__ float g_pd[GRID];            // per-block sum(pred*d)
__device__ float g_d [GRID];            // per-block sum(d)
__device__ float g_mx[GRID];            // per-block max(d)
__device__ unsigned int g_barA = 0;     // phase-A arrival counter
__device__ unsigned int g_ticket = 0;   // phase-B completion counter

union SmemU {
    struct {                            // phase A
        unsigned int tb[H];
        unsigned int hm[H];
        unsigned int Lm[8], Rm[8];
    } a;
    struct {                            // phase B: 4 rows, each padded [W|W|W]
        float s[4][3*W];
    } b;
};

__global__ void __launch_bounds__(256, 4)
k_fused(const float* __restrict__ logits, const int* __restrict__ target,
        float* __restrict__ out) {
    __shared__ SmemU u;
    __shared__ float rs[8], rp[8], rm[8];
    __shared__ bool amLast;

    int bid = blockIdx.x;
    int tid = threadIdx.x;
    int w = tid >> 5, lane = tid & 31;

    // ====== Prefetch logits (independent of everything; hides DRAM latency) =
    int pb = bid >> 6;                  // phase-B image
    int i0 = (bid & 63) * 4;            // phase-B first row (same 32-row slab)
    int j = tid;                        // phase-B column
    float xl[4];
    #pragma unroll
    for (int r = 0; r < 4; r++)
        xl[r] = logits[(pb * H + i0 + r) * W + j];

    // ====== Phase A (blocks 0..63): (image, 32-col group) full-height stripe =
    if (bid < PREP_BLOCKS) {
        int b = bid >> 3;
        int g = bid & 7;
        const int* t = target + b * NPIX;
        int colbase = g << 5;

        // pack: warp w packs rows 32w..32w+31; batch 16 loads -> 16 ballots
        #pragma unroll
        for (int batch = 0; batch < 2; batch++) {
            int v[16];
            #pragma unroll
            for (int r = 0; r < 16; r++) {
                int i = (w << 5) + batch * 16 + r;
                v[r] = t[i * W + colbase + lane];
            }
            #pragma unroll
            for (int r = 0; r < 16; r++) {
                unsigned int m = __ballot_sync(0xffffffffu, v[r] != 0);
                if (lane == 0) u.a.tb[(w << 5) + batch * 16 + r] = m;
            }
        }
        // halo columns (lane = row within slab)
        {
            int i = (w << 5) + lane;
            int Lv = (g > 0) ? t[i * W + colbase - 1]  : 0;
            int Rv = (g < 7) ? t[i * W + colbase + 32] : 0;
            unsigned int lm  = __ballot_sync(0xffffffffu, Lv != 0);
            unsigned int rm2 = __ballot_sync(0xffffffffu, Rv != 0);
            if (lane == 0) { u.a.Lm[w] = lm; u.a.Rm[w] = rm2; }
        }
        __syncthreads();

        // horizontal 3-AND (thread = row)
        {
            int i = tid;
            unsigned int c  = u.a.tb[i];
            unsigned int Lb = (u.a.Lm[i >> 5] >> (i & 31)) & 1u;
            unsigned int Rb = (u.a.Rm[i >> 5] >> (i & 31)) & 1u;
            unsigned int lf = (c << 1) | Lb;
            unsigned int rt = (c >> 1) | (Rb << 31);
            u.a.hm[i] = c & lf & rt;
        }
        __syncthreads();

        // vertical 3-AND -> erosion; boundary = tb ^ er (borders erode false)
        unsigned int bdw;
        {
            int i = tid;
            unsigned int er = (i > 0 && i < H - 1)
                            ? (u.a.hm[i - 1] & u.a.hm[i] & u.a.hm[i + 1]) : 0u;
            if (g == 0) er &= ~1u;
            if (g == 7) er &= ~(1u << 31);
            bdw = u.a.tb[i] ^ er;
        }
        __syncthreads();
        u.a.tb[tid] = bdw;
        __syncthreads();

        // 32x32 bit transpose per warp; lane j gets column j's slab bits
        unsigned int word = u.a.tb[(w << 5) + lane];
        unsigned int v = 0u;
        #pragma unroll
        for (int jj = 0; jj < 32; jj++) {
            unsigned int bm = __ballot_sync(0xffffffffu, (word >> jj) & 1u);
            if (lane == jj) v = bm;
        }
        g_cm[((b * W) + colbase + lane) * 8 + w] = v;

        __threadfence();
        __syncthreads();
        if (tid == 0) atomicAdd(&g_barA, 1u);
    }

    // ====== Grid barrier (prep blocks are in wave 1 by bid order) ===========
    if (tid == 0) {
        while (*(volatile unsigned int*)&g_barA < PREP_BLOCKS) __nanosleep(32);
    }
    __syncthreads();

    // ====== Phase B: vertical distance from bitmask + exact min-plus ========
    const uint4* cmp = (const uint4*)&g_cm[((pb * W) + j) * 8];
    uint4 lov = cmp[0], hiv = cmp[1];
    unsigned int cm[8] = {lov.x, lov.y, lov.z, lov.w, hiv.x, hiv.y, hiv.z, hiv.w};

    int ws = i0 >> 5;
    int P = -1000000, N = 1000000;
    #pragma unroll
    for (int k = 0; k < 8; k++) {
        if (k < ws && cm[k]) P = (k << 5) + 31 - __clz(cm[k]);
        if (k > ws && cm[k] && N == 1000000) N = (k << 5) + __ffs(cm[k]) - 1;
    }
    unsigned int vw = cm[ws];

    #pragma unroll
    for (int r = 0; r < 4; r++) {
        int i = i0 + r, bi = i & 31;
        unsigned int below = vw & (0xFFFFFFFFu >> (31 - bi));
        unsigned int above = vw & (0xFFFFFFFFu << bi);
        int last = below ? ((ws << 5) + 31 - __clz(below)) : P;
        int nxt  = above ? ((ws << 5) + __ffs(above) - 1)  : N;
        int f = min(min(i - last, nxt - i), 10000);      // BIG clip (1e4)
        u.b.s[r][j] = 1e30f;                             // left pad
        u.b.s[r][2 * W + j] = 1e30f;                     // right pad
        u.b.s[r][W + j] = (float)(f * f);                // exact in fp32
    }
    __syncthreads();

    // exact min-plus per pixel, per-lane early exit
    float sd = 0.f, sp = 0.f, mxv = 0.f;
    #pragma unroll
    for (int r = 0; r < 4; r++) {
        const float* s = u.b.s[r];
        float m = s[W + j];
        int o = 1;
        while ((float)(o * o) < m) {
            float o2 = (float)(o * o);
            m = fminf(m, s[W + j - o] + o2);
            m = fminf(m, s[W + j + o] + o2);
            o++;
        }
        float d = sqrtf(m);
        float pred = 1.f / (1.f + __expf(-xl[r]));
        sd += d;
        sp += pred * d;
        mxv = fmaxf(mxv, d);
    }

    // deterministic block reduction -> per-block partials
    #pragma unroll
    for (int o = 16; o; o >>= 1) {
        sd  += __shfl_down_sync(0xffffffffu, sd,  o);
        sp  += __shfl_down_sync(0xffffffffu, sp,  o);
        mxv  = fmaxf(mxv, __shfl_down_sync(0xffffffffu, mxv, o));
    }
    if (lane == 0) { rs[w] = sd; rp[w] = sp; rm[w] = mxv; }
    __syncthreads();
    if (tid == 0) {
        float S = 0.f, Pp = 0.f, M = 0.f;
        #pragma unroll
        for (int k = 0; k < 8; k++) { S += rs[k]; Pp += rp[k]; M = fmaxf(M, rm[k]); }
        g_d[bid] = S; g_pd[bid] = Pp; g_mx[bid] = M;
        __threadfence();
        unsigned int tk = atomicAdd(&g_ticket, 1u);
        amLast = (tk == GRID - 1);
    }
    __syncthreads();
    if (!amLast) return;

    // ====== Final reduction (last block), deterministic =====================
    {
        double sdd = 0.0, spp = 0.0;
        float mxx = 0.f;
        #pragma unroll
        for (int k = 0; k < 2; k++) {
            int rr = w * 64 + k * 32 + lane;
            sdd += (double)g_d[rr];
            spp += (double)g_pd[rr];
            mxx = fmaxf(mxx, g_mx[rr]);
        }
        #pragma unroll
        for (int o = 16; o; o >>= 1) {
            sdd += __shfl_down_sync(0xffffffffu, sdd, o);
            spp += __shfl_down_sync(0xffffffffu, spp, o);
            mxx  = fmaxf(mxx, __shfl_down_sync(0xffffffffu, mxx, o));
        }
        __shared__ double sper[BB];
        if (lane == 0)
            sper[w] = spp / (sdd + 1e-7 * ((double)mxx + 1e-7));
        __syncthreads();
        if (tid == 0) {
            double acc = 0.0;
            #pragma unroll
            for (int k = 0; k < BB; k++) acc += sper[k];
            out[0] = (float)(acc / BB);
            g_ticket = 0;                 // reset for next graph replay
            g_barA = 0;
        }
    }
}

extern "C" void kernel_launch(void* const* d_in, const int* in_sizes, int n_in,
                              void* d_out, int out_size) {
    const float* logits = (const float*)d_in[0];
    const int*   target = (const int*)d_in[1];
    float* out = (float*)d_out;

    k_fused<<<GRID, 256>>>(logits, target, out);
}